// round 2
// baseline (speedup 1.0000x reference)
#include <cuda_runtime.h>
#include <cuda_bf16.h>

#define N_NODES 50000
#define N_EDGES 400000
#define F_NODE 64
#define F_EDGE 16
#define HIDDEN 128
#define DEPTH 3

#define TILE_E 64

typedef unsigned long long ull;

// ---------------- scratch (static device memory; no allocs allowed) ----------------
__device__ float g_h [(size_t)N_EDGES * HIDDEN];   // 204.8 MB
__device__ float g_hn[(size_t)N_EDGES * HIDDEN];   // 204.8 MB
__device__ float g_agg[(size_t)N_NODES * HIDDEN];  // 25.6 MB

// ---------------- f32x2 helpers (packed fp32 FMA) ----------------
__device__ __forceinline__ ull pk(float a) {
    ull r; asm("mov.b64 %0, {%1, %1};" : "=l"(r) : "f"(a)); return r;
}
__device__ __forceinline__ void fma2(ull& d, ull a, ull b) {
    asm("fma.rn.f32x2 %0, %1, %2, %0;" : "+l"(d) : "l"(a), "l"(b));
}
__device__ __forceinline__ float2 up(ull v) {
    float2 f; asm("mov.b64 {%0, %1}, %2;" : "=f"(f.x), "=f"(f.y) : "l"(v)); return f;
}

// ---------------- GEMM micro-kernel ----------------
// 128 threads; thread (tx in [0,16), ty in [0,8)) computes an 8(edge) x 8(col) tile.
// Ws: [K][128] row-major in smem. ins: [TILE_E][PADW*4] row-major in smem.
template<int K, int PADW>
__device__ __forceinline__ void gemm_tile(const float* Ws, const float* ins,
                                          int tx, int ty, ull acc[8][4]) {
    const ulonglong2* Wu = reinterpret_cast<const ulonglong2*>(Ws);
    const float4*     in4 = reinterpret_cast<const float4*>(ins);
    #pragma unroll 1
    for (int k = 0; k < K; k += 4) {
        ulonglong2 w0a = Wu[(k+0)*32 + tx*2], w0b = Wu[(k+0)*32 + tx*2 + 1];
        ulonglong2 w1a = Wu[(k+1)*32 + tx*2], w1b = Wu[(k+1)*32 + tx*2 + 1];
        ulonglong2 w2a = Wu[(k+2)*32 + tx*2], w2b = Wu[(k+2)*32 + tx*2 + 1];
        ulonglong2 w3a = Wu[(k+3)*32 + tx*2], w3b = Wu[(k+3)*32 + tx*2 + 1];
        #pragma unroll
        for (int i = 0; i < 8; ++i) {
            float4 av = in4[(ty*8 + i)*PADW + (k >> 2)];
            ull a;
            a = pk(av.x);
            fma2(acc[i][0], a, w0a.x); fma2(acc[i][1], a, w0a.y);
            fma2(acc[i][2], a, w0b.x); fma2(acc[i][3], a, w0b.y);
            a = pk(av.y);
            fma2(acc[i][0], a, w1a.x); fma2(acc[i][1], a, w1a.y);
            fma2(acc[i][2], a, w1b.x); fma2(acc[i][3], a, w1b.y);
            a = pk(av.z);
            fma2(acc[i][0], a, w2a.x); fma2(acc[i][1], a, w2a.y);
            fma2(acc[i][2], a, w2b.x); fma2(acc[i][3], a, w2b.y);
            a = pk(av.w);
            fma2(acc[i][0], a, w3a.x); fma2(acc[i][1], a, w3a.y);
            fma2(acc[i][2], a, w3b.x); fma2(acc[i][3], a, w3b.y);
        }
    }
}

__device__ __forceinline__ void store_tile(ull acc[8][4], const float bj[8],
                                           float* out, int r0, int tx, int ty, int rmax) {
    float4* out4 = reinterpret_cast<float4*>(out);
    #pragma unroll
    for (int i = 0; i < 8; ++i) {
        int r = r0 + ty*8 + i;
        if (r >= rmax) continue;
        float2 p0 = up(acc[i][0]), p1 = up(acc[i][1]);
        float2 p2 = up(acc[i][2]), p3 = up(acc[i][3]);
        float4 v0 = make_float4(fmaxf(p0.x + bj[0], 0.f), fmaxf(p0.y + bj[1], 0.f),
                                fmaxf(p1.x + bj[2], 0.f), fmaxf(p1.y + bj[3], 0.f));
        float4 v1 = make_float4(fmaxf(p2.x + bj[4], 0.f), fmaxf(p2.y + bj[5], 0.f),
                                fmaxf(p3.x + bj[6], 0.f), fmaxf(p3.y + bj[7], 0.f));
        out4[(size_t)r*32 + tx*2    ] = v0;
        out4[(size_t)r*32 + tx*2 + 1] = v1;
    }
}

// ---------------- kernel 1: h0 = relu([x[row] ; edge_attr] @ W1 + b1) ----------------
#define INIT_K   80
#define INIT_PAD 84
#define INIT_SMEM ((INIT_K*HIDDEN + TILE_E*INIT_PAD) * 4)

__global__ __launch_bounds__(128) void k_edge_init(
    const float* __restrict__ x, const float* __restrict__ ea, const int* __restrict__ row,
    const float* __restrict__ W, const float* __restrict__ b, float* __restrict__ hout)
{
    extern __shared__ float smem[];
    float* Ws  = smem;
    float* ins = smem + INIT_K*HIDDEN;
    int tid = threadIdx.x;
    {
        const float4* Wg = (const float4*)W;
        float4* Wd = (float4*)Ws;
        for (int i = tid; i < INIT_K*HIDDEN/4; i += 128) Wd[i] = Wg[i];
    }
    int tx = tid & 15, ty = tid >> 4;
    float bj[8];
    #pragma unroll
    for (int t = 0; t < 8; ++t) bj[t] = __ldg(&b[tx*8 + t]);
    int wid = tid >> 5, lane = tid & 31;
    const float4* x4  = (const float4*)x;
    const float4* ea4 = (const float4*)ea;
    float4* ins4 = (float4*)ins;
    const int NT = N_EDGES / TILE_E;
    for (int tile = blockIdx.x; tile < NT; tile += gridDim.x) {
        __syncthreads();
        for (int el = wid; el < TILE_E; el += 4) {
            int e = tile*TILE_E + el;
            int r = __ldg(&row[e]);
            if (lane < 16)      ins4[el*(INIT_PAD/4) + lane] = x4[(size_t)r*16 + lane];
            else if (lane < 20) ins4[el*(INIT_PAD/4) + lane] = ea4[(size_t)e*4 + (lane - 16)];
        }
        __syncthreads();
        ull acc[8][4];
        #pragma unroll
        for (int i = 0; i < 8; ++i) { acc[i][0]=0; acc[i][1]=0; acc[i][2]=0; acc[i][3]=0; }
        gemm_tile<INIT_K, INIT_PAD/4>(Ws, ins, tx, ty, acc);
        store_tile(acc, bj, hout, tile*TILE_E, tx, ty, 0x7fffffff);
    }
}

// ---------------- kernel 2: scatter-add h into agg by col (vector REDG) ----------------
__global__ __launch_bounds__(256) void k_scatter(
    const float* __restrict__ h, const int* __restrict__ col, float* __restrict__ agg)
{
    int idx = blockIdx.x * 256 + threadIdx.x;
    int e = idx >> 5, c = idx & 31;
    if (e >= N_EDGES) return;
    const float4* h4 = (const float4*)h;
    float4 v = h4[(size_t)e*32 + c];
    int n = __ldg(&col[e]);
    float* dst = agg + (size_t)n*HIDDEN + c*4;
    asm volatile("red.global.add.v4.f32 [%0], {%1, %2, %3, %4};"
                 :: "l"(dst), "f"(v.x), "f"(v.y), "f"(v.z), "f"(v.w) : "memory");
}

// ---------------- kernel 3: h' = relu((agg[row] - h[e^1]) @ Wc + bc) ----------------
#define CONV_PAD 132
#define CONV_SMEM ((HIDDEN*HIDDEN + TILE_E*CONV_PAD) * 4)

__global__ __launch_bounds__(128) void k_conv(
    const float* __restrict__ h, const float* __restrict__ agg, const int* __restrict__ row,
    const float* __restrict__ W, const float* __restrict__ b, float* __restrict__ hout)
{
    extern __shared__ float smem[];
    float* Ws  = smem;
    float* ins = smem + HIDDEN*HIDDEN;
    int tid = threadIdx.x;
    {
        const float4* Wg = (const float4*)W;
        float4* Wd = (float4*)Ws;
        for (int i = tid; i < HIDDEN*HIDDEN/4; i += 128) Wd[i] = Wg[i];
    }
    int tx = tid & 15, ty = tid >> 4;
    float bj[8];
    #pragma unroll
    for (int t = 0; t < 8; ++t) bj[t] = __ldg(&b[tx*8 + t]);
    int wid = tid >> 5, lane = tid & 31;
    const float4* h4   = (const float4*)h;
    const float4* agg4 = (const float4*)agg;
    float4* ins4 = (float4*)ins;
    const int NT = N_EDGES / TILE_E;
    for (int tile = blockIdx.x; tile < NT; tile += gridDim.x) {
        __syncthreads();
        for (int el = wid; el < TILE_E; el += 4) {
            int e = tile*TILE_E + el;
            int r = __ldg(&row[e]);
            float4 a  = agg4[(size_t)r*32 + lane];
            float4 rv = h4[(size_t)(e ^ 1)*32 + lane];
            ins4[el*(CONV_PAD/4) + lane] = make_float4(a.x - rv.x, a.y - rv.y,
                                                       a.z - rv.z, a.w - rv.w);
        }
        __syncthreads();
        ull acc[8][4];
        #pragma unroll
        for (int i = 0; i < 8; ++i) { acc[i][0]=0; acc[i][1]=0; acc[i][2]=0; acc[i][3]=0; }
        gemm_tile<HIDDEN, CONV_PAD/4>(Ws, ins, tx, ty, acc);
        store_tile(acc, bj, hout, tile*TILE_E, tx, ty, 0x7fffffff);
    }
}

// ---------------- kernel 4: out = relu([x ; s] @ W2 + b2) ----------------
#define FIN_K   192
#define FIN_PAD 196
#define FIN_SMEM ((FIN_K*HIDDEN + TILE_E*FIN_PAD) * 4)

__global__ __launch_bounds__(128) void k_final(
    const float* __restrict__ x, const float* __restrict__ agg,
    const float* __restrict__ W, const float* __restrict__ b, float* __restrict__ out)
{
    extern __shared__ float smem[];
    float* Ws  = smem;
    float* ins = smem + FIN_K*HIDDEN;
    int tid = threadIdx.x;
    {
        const float4* Wg = (const float4*)W;
        float4* Wd = (float4*)Ws;
        for (int i = tid; i < FIN_K*HIDDEN/4; i += 128) Wd[i] = Wg[i];
    }
    int tx = tid & 15, ty = tid >> 4;
    float bj[8];
    #pragma unroll
    for (int t = 0; t < 8; ++t) bj[t] = __ldg(&b[tx*8 + t]);
    int wid = tid >> 5, lane = tid & 31;
    const float4* x4   = (const float4*)x;
    const float4* agg4 = (const float4*)agg;
    float4* ins4 = (float4*)ins;
    const int NT = (N_NODES + TILE_E - 1) / TILE_E;
    for (int tile = blockIdx.x; tile < NT; tile += gridDim.x) {
        __syncthreads();
        for (int nl = wid; nl < TILE_E; nl += 4) {
            int n = tile*TILE_E + nl;
            if (n < N_NODES) {
                if (lane < 16) ins4[nl*(FIN_PAD/4) + lane] = x4[(size_t)n*16 + lane];
                ins4[nl*(FIN_PAD/4) + 16 + lane] = agg4[(size_t)n*32 + lane];
            } else {
                if (lane < 16) ins4[nl*(FIN_PAD/4) + lane] = make_float4(0,0,0,0);
                ins4[nl*(FIN_PAD/4) + 16 + lane] = make_float4(0,0,0,0);
            }
        }
        __syncthreads();
        ull acc[8][4];
        #pragma unroll
        for (int i = 0; i < 8; ++i) { acc[i][0]=0; acc[i][1]=0; acc[i][2]=0; acc[i][3]=0; }
        gemm_tile<FIN_K, FIN_PAD/4>(Ws, ins, tx, ty, acc);
        store_tile(acc, bj, out, tile*TILE_E, tx, ty, N_NODES);
    }
}

// ---------------- launch ----------------
extern "C" void kernel_launch(void* const* d_in, const int* in_sizes, int n_in,
                              void* d_out, int out_size)
{
    const float* x  = (const float*)d_in[0];
    const float* ea = (const float*)d_in[1];
    const int*   ei = (const int*)  d_in[2];
    const float* W1 = (const float*)d_in[3];
    const float* b1 = (const float*)d_in[4];
    const float* Wc = (const float*)d_in[5];
    const float* bc = (const float*)d_in[6];
    const float* W2 = (const float*)d_in[7];
    const float* b2 = (const float*)d_in[8];
    float* out = (float*)d_out;
    const int* row = ei;
    const int* col = ei + N_EDGES;

    void *ph, *phn, *pagg;
    cudaGetSymbolAddress(&ph,  g_h);
    cudaGetSymbolAddress(&phn, g_hn);
    cudaGetSymbolAddress(&pagg, g_agg);
    float* hb  = (float*)ph;
    float* hnb = (float*)phn;
    float* agg = (float*)pagg;

    cudaFuncSetAttribute(k_edge_init, cudaFuncAttributeMaxDynamicSharedMemorySize, INIT_SMEM);
    cudaFuncSetAttribute(k_conv,      cudaFuncAttributeMaxDynamicSharedMemorySize, CONV_SMEM);
    cudaFuncSetAttribute(k_final,     cudaFuncAttributeMaxDynamicSharedMemorySize, FIN_SMEM);

    k_edge_init<<<444, 128, INIT_SMEM>>>(x, ea, row, W1, b1, hb);

    float* cur = hb;
    float* nxt = hnb;
    for (int d = 0; d < DEPTH; ++d) {
        cudaMemsetAsync(agg, 0, (size_t)N_NODES * HIDDEN * sizeof(float));
        k_scatter<<<(N_EDGES * 32) / 256, 256>>>(cur, col, agg);
        k_conv<<<296, 128, CONV_SMEM>>>(cur, agg, row,
                                        Wc + (size_t)d * HIDDEN * HIDDEN,
                                        bc + (size_t)d * HIDDEN, nxt);
        float* t = cur; cur = nxt; nxt = t;
    }

    cudaMemsetAsync(agg, 0, (size_t)N_NODES * HIDDEN * sizeof(float));
    k_scatter<<<(N_EDGES * 32) / 256, 256>>>(cur, col, agg);
    k_final<<<148, 128, FIN_SMEM>>>(x, agg, W2, b2, out);
}

// round 4
// speedup vs baseline: 1.6031x; 1.6031x over previous
#include <cuda_runtime.h>
#include <cuda_bf16.h>
#include <cstdint>

#define N_NODES 50000
#define N_EDGES 400000
#define F_NODE 64
#define F_EDGE 16
#define HIDDEN 128
#define DEPTH 3

typedef unsigned long long ull;

// ---------------- scratch (static device memory; no allocs allowed) ----------------
__device__ float g_h [(size_t)N_EDGES * HIDDEN];   // 204.8 MB
__device__ float g_hn[(size_t)N_EDGES * HIDDEN];   // 204.8 MB
__device__ float g_agg[(size_t)N_NODES * HIDDEN];  // 25.6 MB

// ================= helpers =================
__device__ __forceinline__ uint32_t smem_u32(const void* p) {
    uint32_t a;
    asm("{ .reg .u64 t; cvta.to.shared.u64 t, %1; cvt.u32.u64 %0, t; }" : "=r"(a) : "l"(p));
    return a;
}

// bf16 hi/lo split of 4 floats -> two 64-bit words of 4 bf16 each
__device__ __forceinline__ void split4(float4 v, ull& hi, ull& lo) {
    __nv_bfloat16 h0 = __float2bfloat16_rn(v.x);
    __nv_bfloat16 h1 = __float2bfloat16_rn(v.y);
    __nv_bfloat16 h2 = __float2bfloat16_rn(v.z);
    __nv_bfloat16 h3 = __float2bfloat16_rn(v.w);
    __nv_bfloat16 l0 = __float2bfloat16_rn(v.x - __bfloat162float(h0));
    __nv_bfloat16 l1 = __float2bfloat16_rn(v.y - __bfloat162float(h1));
    __nv_bfloat16 l2 = __float2bfloat16_rn(v.z - __bfloat162float(h2));
    __nv_bfloat16 l3 = __float2bfloat16_rn(v.w - __bfloat162float(h3));
    uint32_t ha = (uint32_t)__bfloat16_as_ushort(h0) | ((uint32_t)__bfloat16_as_ushort(h1) << 16);
    uint32_t hb = (uint32_t)__bfloat16_as_ushort(h2) | ((uint32_t)__bfloat16_as_ushort(h3) << 16);
    uint32_t la = (uint32_t)__bfloat16_as_ushort(l0) | ((uint32_t)__bfloat16_as_ushort(l1) << 16);
    uint32_t lb = (uint32_t)__bfloat16_as_ushort(l2) | ((uint32_t)__bfloat16_as_ushort(l3) << 16);
    hi = (ull)ha | ((ull)hb << 32);
    lo = (ull)la | ((ull)lb << 32);
}

__device__ __forceinline__ void ldsm4(uint32_t* r, uint32_t addr) {
    asm volatile("ldmatrix.sync.aligned.m8n8.x4.shared.b16 {%0,%1,%2,%3}, [%4];"
                 : "=r"(r[0]), "=r"(r[1]), "=r"(r[2]), "=r"(r[3]) : "r"(addr));
}

__device__ __forceinline__ void mma16816(float* d, const uint32_t* a, const uint32_t* b) {
    asm volatile("mma.sync.aligned.m16n8k16.row.col.f32.bf16.bf16.f32 "
                 "{%0,%1,%2,%3}, {%4,%5,%6,%7}, {%8,%9}, {%0,%1,%2,%3};"
                 : "+f"(d[0]), "+f"(d[1]), "+f"(d[2]), "+f"(d[3])
                 : "r"(a[0]), "r"(a[1]), "r"(a[2]), "r"(a[3]), "r"(b[0]), "r"(b[1]));
}

// SMEM layout (bf16 matrices, row stride SB=136 elems = 272 B, 16B-aligned rows)
#define SB 136
#define MAT_BYTES (128 * SB * 2)       // 34816
#define SM_BIAS 0                      // 512 B
#define SM_AHI  512
#define SM_ALO  (SM_AHI + MAT_BYTES)
#define SM_BHI  (SM_ALO + MAT_BYTES)
#define SM_BLO  (SM_BHI + MAT_BYTES)
#define SM_TOT  (SM_BLO + MAT_BYTES)   // 139776

// ---------------- MMA mainloop + epilogue shared by init/conv ----------------
// Each of 8 warps computes rows [warp*16, warp*16+16) x 128 cols.
template<int KSTEPS>
__device__ __forceinline__ void mma_tile_and_store(
    uint32_t aH, uint32_t aL, uint32_t bH, uint32_t bL,
    const float* bs, float* out, int tile, int warp, int g, int tq)
{
    float acc[16][4];
    #pragma unroll
    for (int p = 0; p < 16; ++p)
        #pragma unroll
        for (int q = 0; q < 4; ++q) acc[p][q] = 0.f;

    for (int ks = 0; ks < KSTEPS; ++ks) {
        uint32_t ah[4], al[4];
        ldsm4(ah, aH + ks * 32);
        ldsm4(al, aL + ks * 32);
        #pragma unroll
        for (int p = 0; p < 8; ++p) {
            uint32_t bh[4], bl[4];
            ldsm4(bh, bH + p * (16 * SB * 2) + ks * 32);
            ldsm4(bl, bL + p * (16 * SB * 2) + ks * 32);
            mma16816(acc[2*p],   ah, bh);
            mma16816(acc[2*p],   ah, bl);
            mma16816(acc[2*p],   al, bh);
            mma16816(acc[2*p+1], ah, bh + 2);
            mma16816(acc[2*p+1], ah, bl + 2);
            mma16816(acc[2*p+1], al, bh + 2);
        }
    }

    size_t base = ((size_t)tile * 128 + warp * 16) * 128;
    float* o0 = out + base + g * 128;
    float* o1 = out + base + (g + 8) * 128;
    #pragma unroll
    for (int p = 0; p < 16; ++p) {
        int c0 = p * 8 + tq * 2;
        float2 v0 = make_float2(fmaxf(acc[p][0] + bs[c0], 0.f),
                                fmaxf(acc[p][1] + bs[c0+1], 0.f));
        float2 v1 = make_float2(fmaxf(acc[p][2] + bs[c0], 0.f),
                                fmaxf(acc[p][3] + bs[c0+1], 0.f));
        *(float2*)(o0 + c0) = v0;
        *(float2*)(o1 + c0) = v1;
    }
}

// ---------------- conv: h' = relu((agg[row] - h[e^1]) @ Wc + bc) ----------------
__global__ __launch_bounds__(256, 1) void k_conv_mma(
    const float* __restrict__ h, const float* __restrict__ agg,
    const int* __restrict__ row, const float* __restrict__ W,
    const float* __restrict__ b, float* __restrict__ hout)
{
    extern __shared__ char smem[];
    uint32_t sb = smem_u32(smem);
    int tid = threadIdx.x, warp = tid >> 5, lane = tid & 31;
    int g = lane >> 2, tq = lane & 3;

    float* bs = (float*)(smem + SM_BIAS);
    if (tid < 128) bs[tid] = __ldg(&b[tid]);

    // B = W^T hi/lo (once per CTA): Bs[n][k] = W[k*128+n]
    {
        int n = tid >> 1, kh = (tid & 1) * 64;
        char* Bh = smem + SM_BHI; char* Bl = smem + SM_BLO;
        #pragma unroll
        for (int c = 0; c < 16; ++c) {
            int k = kh + c * 4;
            float4 v = make_float4(__ldg(&W[(k+0)*128 + n]), __ldg(&W[(k+1)*128 + n]),
                                   __ldg(&W[(k+2)*128 + n]), __ldg(&W[(k+3)*128 + n]));
            ull hi, lo; split4(v, hi, lo);
            uint32_t off = (uint32_t)(n * SB + k) * 2;
            *(ull*)(Bh + off) = hi; *(ull*)(Bl + off) = lo;
        }
    }
    __syncthreads();

    // per-lane ldmatrix addresses
    int a_row = (lane & 7) + ((lane >> 3) & 1) * 8;
    int a_col = (lane >> 4) * 8;
    uint32_t aH = sb + SM_AHI + (uint32_t)((warp*16 + a_row) * SB + a_col) * 2;
    uint32_t aL = aH + MAT_BYTES;
    int b_row = (lane & 7) + ((lane >> 4) & 1) * 8;
    int b_col = ((lane >> 3) & 1) * 8;
    uint32_t bH = sb + SM_BHI + (uint32_t)(b_row * SB + b_col) * 2;
    uint32_t bL = bH + MAT_BYTES;

    const float4* agg4 = (const float4*)agg;
    const float4* h4   = (const float4*)h;
    char* Ah = smem + SM_AHI; char* Al = smem + SM_ALO;
    const int NT = N_EDGES / 128;

    for (int tile = blockIdx.x; tile < NT; tile += gridDim.x) {
        {
            int r = tid >> 1, kh = (tid & 1) * 64;
            int e = tile * 128 + r;
            int rr = __ldg(&row[e]);
            const float4* ap = agg4 + (size_t)rr * 32 + kh / 4;
            const float4* rp = h4 + (size_t)(e ^ 1) * 32 + kh / 4;
            #pragma unroll
            for (int c = 0; c < 16; ++c) {
                float4 a = ap[c], rv = rp[c];
                float4 d = make_float4(a.x - rv.x, a.y - rv.y, a.z - rv.z, a.w - rv.w);
                ull hi, lo; split4(d, hi, lo);
                uint32_t off = (uint32_t)(r * SB + kh + c * 4) * 2;
                *(ull*)(Ah + off) = hi; *(ull*)(Al + off) = lo;
            }
        }
        __syncthreads();
        mma_tile_and_store<8>(aH, aL, bH, bL, bs, hout, tile, warp, g, tq);
        __syncthreads();
    }
}

// ---------------- init: h0 = relu([x[row] ; ea] @ W1 + b1), K=80 ----------------
__global__ __launch_bounds__(256, 1) void k_init_mma(
    const float* __restrict__ x, const float* __restrict__ ea,
    const int* __restrict__ row, const float* __restrict__ W,
    const float* __restrict__ b, float* __restrict__ hout)
{
    extern __shared__ char smem[];
    uint32_t sb = smem_u32(smem);
    int tid = threadIdx.x, warp = tid >> 5, lane = tid & 31;
    int g = lane >> 2, tq = lane & 3;

    float* bs = (float*)(smem + SM_BIAS);
    if (tid < 128) bs[tid] = __ldg(&b[tid]);

    // B = W1^T hi/lo, K=80
    {
        int n = tid >> 1, kh = (tid & 1) * 64;
        int nch = (tid & 1) ? 4 : 16;
        char* Bh = smem + SM_BHI; char* Bl = smem + SM_BLO;
        for (int c = 0; c < nch; ++c) {
            int k = kh + c * 4;
            float4 v = make_float4(__ldg(&W[(k+0)*128 + n]), __ldg(&W[(k+1)*128 + n]),
                                   __ldg(&W[(k+2)*128 + n]), __ldg(&W[(k+3)*128 + n]));
            ull hi, lo; split4(v, hi, lo);
            uint32_t off = (uint32_t)(n * SB + k) * 2;
            *(ull*)(Bh + off) = hi; *(ull*)(Bl + off) = lo;
        }
    }
    __syncthreads();

    int a_row = (lane & 7) + ((lane >> 3) & 1) * 8;
    int a_col = (lane >> 4) * 8;
    uint32_t aH = sb + SM_AHI + (uint32_t)((warp*16 + a_row) * SB + a_col) * 2;
    uint32_t aL = aH + MAT_BYTES;
    int b_row = (lane & 7) + ((lane >> 4) & 1) * 8;
    int b_col = ((lane >> 3) & 1) * 8;
    uint32_t bH = sb + SM_BHI + (uint32_t)(b_row * SB + b_col) * 2;
    uint32_t bL = bH + MAT_BYTES;

    const float4* x4  = (const float4*)x;
    const float4* ea4 = (const float4*)ea;
    char* Ah = smem + SM_AHI; char* Al = smem + SM_ALO;
    const int NT = N_EDGES / 128;

    for (int tile = blockIdx.x; tile < NT; tile += gridDim.x) {
        {
            int r = tid >> 1;
            int e = tile * 128 + r;
            int rr = __ldg(&row[e]);
            if ((tid & 1) == 0) {
                const float4* xp = x4 + (size_t)rr * 16;
                #pragma unroll
                for (int c = 0; c < 16; ++c) {
                    ull hi, lo; split4(xp[c], hi, lo);
                    uint32_t off = (uint32_t)(r * SB + c * 4) * 2;
                    *(ull*)(Ah + off) = hi; *(ull*)(Al + off) = lo;
                }
            } else {
                const float4* ep = ea4 + (size_t)e * 4;
                #pragma unroll
                for (int c = 0; c < 4; ++c) {
                    ull hi, lo; split4(ep[c], hi, lo);
                    uint32_t off = (uint32_t)(r * SB + 64 + c * 4) * 2;
                    *(ull*)(Ah + off) = hi; *(ull*)(Al + off) = lo;
                }
            }
        }
        __syncthreads();
        mma_tile_and_store<5>(aH, aL, bH, bL, bs, hout, tile, warp, g, tq);
        __syncthreads();
    }
}

// ---------------- scatter-add h into agg by col (vector REDG) ----------------
__global__ __launch_bounds__(256) void k_scatter(
    const float* __restrict__ h, const int* __restrict__ col, float* __restrict__ agg)
{
    int idx = blockIdx.x * 256 + threadIdx.x;
    int e = idx >> 5, c = idx & 31;
    if (e >= N_EDGES) return;
    const float4* h4 = (const float4*)h;
    float4 v = h4[(size_t)e*32 + c];
    int n = __ldg(&col[e]);
    float* dst = agg + (size_t)n*HIDDEN + c*4;
    asm volatile("red.global.add.v4.f32 [%0], {%1, %2, %3, %4};"
                 :: "l"(dst), "f"(v.x), "f"(v.y), "f"(v.z), "f"(v.w) : "memory");
}

// ================= k_final (FFMA path, unchanged from passing round) =================
#define TILE_E 64
__device__ __forceinline__ ull pk(float a) {
    ull r; asm("mov.b64 %0, {%1, %1};" : "=l"(r) : "f"(a)); return r;
}
__device__ __forceinline__ void fma2(ull& d, ull a, ull b) {
    asm("fma.rn.f32x2 %0, %1, %2, %0;" : "+l"(d) : "l"(a), "l"(b));
}
__device__ __forceinline__ float2 up(ull v) {
    float2 f; asm("mov.b64 {%0, %1}, %2;" : "=f"(f.x), "=f"(f.y) : "l"(v)); return f;
}

template<int K, int PADW>
__device__ __forceinline__ void gemm_tile(const float* Ws, const float* ins,
                                          int tx, int ty, ull acc[8][4]) {
    const ulonglong2* Wu = reinterpret_cast<const ulonglong2*>(Ws);
    const float4*     in4 = reinterpret_cast<const float4*>(ins);
    #pragma unroll 1
    for (int k = 0; k < K; k += 4) {
        ulonglong2 w0a = Wu[(k+0)*32 + tx*2], w0b = Wu[(k+0)*32 + tx*2 + 1];
        ulonglong2 w1a = Wu[(k+1)*32 + tx*2], w1b = Wu[(k+1)*32 + tx*2 + 1];
        ulonglong2 w2a = Wu[(k+2)*32 + tx*2], w2b = Wu[(k+2)*32 + tx*2 + 1];
        ulonglong2 w3a = Wu[(k+3)*32 + tx*2], w3b = Wu[(k+3)*32 + tx*2 + 1];
        #pragma unroll
        for (int i = 0; i < 8; ++i) {
            float4 av = in4[(ty*8 + i)*PADW + (k >> 2)];
            ull a;
            a = pk(av.x);
            fma2(acc[i][0], a, w0a.x); fma2(acc[i][1], a, w0a.y);
            fma2(acc[i][2], a, w0b.x); fma2(acc[i][3], a, w0b.y);
            a = pk(av.y);
            fma2(acc[i][0], a, w1a.x); fma2(acc[i][1], a, w1a.y);
            fma2(acc[i][2], a, w1b.x); fma2(acc[i][3], a, w1b.y);
            a = pk(av.z);
            fma2(acc[i][0], a, w2a.x); fma2(acc[i][1], a, w2a.y);
            fma2(acc[i][2], a, w2b.x); fma2(acc[i][3], a, w2b.y);
            a = pk(av.w);
            fma2(acc[i][0], a, w3a.x); fma2(acc[i][1], a, w3a.y);
            fma2(acc[i][2], a, w3b.x); fma2(acc[i][3], a, w3b.y);
        }
    }
}

__device__ __forceinline__ void store_tile(ull acc[8][4], const float bj[8],
                                           float* out, int r0, int tx, int ty, int rmax) {
    float4* out4 = reinterpret_cast<float4*>(out);
    #pragma unroll
    for (int i = 0; i < 8; ++i) {
        int r = r0 + ty*8 + i;
        if (r >= rmax) continue;
        float2 p0 = up(acc[i][0]), p1 = up(acc[i][1]);
        float2 p2 = up(acc[i][2]), p3 = up(acc[i][3]);
        float4 v0 = make_float4(fmaxf(p0.x + bj[0], 0.f), fmaxf(p0.y + bj[1], 0.f),
                                fmaxf(p1.x + bj[2], 0.f), fmaxf(p1.y + bj[3], 0.f));
        float4 v1 = make_float4(fmaxf(p2.x + bj[4], 0.f), fmaxf(p2.y + bj[5], 0.f),
                                fmaxf(p3.x + bj[6], 0.f), fmaxf(p3.y + bj[7], 0.f));
        out4[(size_t)r*32 + tx*2    ] = v0;
        out4[(size_t)r*32 + tx*2 + 1] = v1;
    }
}

#define FIN_K   192
#define FIN_PAD 196
#define FIN_SMEM ((FIN_K*HIDDEN + TILE_E*FIN_PAD) * 4)

__global__ __launch_bounds__(128) void k_final(
    const float* __restrict__ x, const float* __restrict__ agg,
    const float* __restrict__ W, const float* __restrict__ b, float* __restrict__ out)
{
    extern __shared__ float smemf[];
    float* Ws  = smemf;
    float* ins = smemf + FIN_K*HIDDEN;
    int tid = threadIdx.x;
    {
        const float4* Wg = (const float4*)W;
        float4* Wd = (float4*)Ws;
        for (int i = tid; i < FIN_K*HIDDEN/4; i += 128) Wd[i] = Wg[i];
    }
    int tx = tid & 15, ty = tid >> 4;
    float bj[8];
    #pragma unroll
    for (int t = 0; t < 8; ++t) bj[t] = __ldg(&b[tx*8 + t]);
    int wid = tid >> 5, lane = tid & 31;
    const float4* x4   = (const float4*)x;
    const float4* agg4 = (const float4*)agg;
    float4* ins4 = (float4*)ins;
    const int NT = (N_NODES + TILE_E - 1) / TILE_E;
    for (int tile = blockIdx.x; tile < NT; tile += gridDim.x) {
        __syncthreads();
        for (int nl = wid; nl < TILE_E; nl += 4) {
            int n = tile*TILE_E + nl;
            if (n < N_NODES) {
                if (lane < 16) ins4[nl*(FIN_PAD/4) + lane] = x4[(size_t)n*16 + lane];
                ins4[nl*(FIN_PAD/4) + 16 + lane] = agg4[(size_t)n*32 + lane];
            } else {
                if (lane < 16) ins4[nl*(FIN_PAD/4) + lane] = make_float4(0,0,0,0);
                ins4[nl*(FIN_PAD/4) + 16 + lane] = make_float4(0,0,0,0);
            }
        }
        __syncthreads();
        ull acc[8][4];
        #pragma unroll
        for (int i = 0; i < 8; ++i) { acc[i][0]=0; acc[i][1]=0; acc[i][2]=0; acc[i][3]=0; }
        gemm_tile<FIN_K, FIN_PAD/4>(Ws, ins, tx, ty, acc);
        store_tile(acc, bj, out, tile*TILE_E, tx, ty, N_NODES);
    }
}

// ---------------- launch ----------------
extern "C" void kernel_launch(void* const* d_in, const int* in_sizes, int n_in,
                              void* d_out, int out_size)
{
    const float* x  = (const float*)d_in[0];
    const float* ea = (const float*)d_in[1];
    const int*   ei = (const int*)  d_in[2];
    const float* W1 = (const float*)d_in[3];
    const float* b1 = (const float*)d_in[4];
    const float* Wc = (const float*)d_in[5];
    const float* bc = (const float*)d_in[6];
    const float* W2 = (const float*)d_in[7];
    const float* b2 = (const float*)d_in[8];
    float* out = (float*)d_out;
    const int* row = ei;
    const int* col = ei + N_EDGES;

    void *ph_, *phn_, *pagg_;
    cudaGetSymbolAddress(&ph_,  g_h);
    cudaGetSymbolAddress(&phn_, g_hn);
    cudaGetSymbolAddress(&pagg_, g_agg);
    float* hb  = (float*)ph_;
    float* hnb = (float*)phn_;
    float* agg = (float*)pagg_;

    cudaFuncSetAttribute(k_init_mma, cudaFuncAttributeMaxDynamicSharedMemorySize, SM_TOT);
    cudaFuncSetAttribute(k_conv_mma, cudaFuncAttributeMaxDynamicSharedMemorySize, SM_TOT);
    cudaFuncSetAttribute(k_final,    cudaFuncAttributeMaxDynamicSharedMemorySize, FIN_SMEM);

    k_init_mma<<<148, 256, SM_TOT>>>(x, ea, row, W1, b1, hb);

    float* cur = hb;
    float* nxt = hnb;
    for (int d = 0; d < DEPTH; ++d) {
        cudaMemsetAsync(agg, 0, (size_t)N_NODES * HIDDEN * sizeof(float));
        k_scatter<<<(N_EDGES * 32) / 256, 256>>>(cur, col, agg);
        k_conv_mma<<<148, 256, SM_TOT>>>(cur, agg, row,
                                         Wc + (size_t)d * HIDDEN * HIDDEN,
                                         bc + (size_t)d * HIDDEN, nxt);
        float* t = cur; cur = nxt; nxt = t;
    }

    cudaMemsetAsync(agg, 0, (size_t)N_NODES * HIDDEN * sizeof(float));
    k_scatter<<<(N_EDGES * 32) / 256, 256>>>(cur, col, agg);
    k_final<<<148, 128, FIN_SMEM>>>(x, agg, W2, b2, out);
}

// round 5
// speedup vs baseline: 1.6685x; 1.0408x over previous
#include <cuda_runtime.h>
#include <cuda_bf16.h>
#include <cstdint>

#define N_NODES 50000
#define N_EDGES 400000
#define F_NODE 64
#define F_EDGE 16
#define HIDDEN 128
#define DEPTH 3

typedef unsigned long long ull;

// ---------------- scratch (static device memory; no allocs allowed) ----------------
__device__ float g_h [(size_t)N_EDGES * HIDDEN];   // 204.8 MB
__device__ float g_hn[(size_t)N_EDGES * HIDDEN];   // 204.8 MB
__device__ float g_agg[(size_t)N_NODES * HIDDEN];  // 25.6 MB

// ================= helpers =================
__device__ __forceinline__ uint32_t smem_u32(const void* p) {
    uint32_t a;
    asm("{ .reg .u64 t; cvta.to.shared.u64 t, %1; cvt.u32.u64 %0, t; }" : "=r"(a) : "l"(p));
    return a;
}

__device__ __forceinline__ void split4(float4 v, ull& hi, ull& lo) {
    __nv_bfloat16 h0 = __float2bfloat16_rn(v.x);
    __nv_bfloat16 h1 = __float2bfloat16_rn(v.y);
    __nv_bfloat16 h2 = __float2bfloat16_rn(v.z);
    __nv_bfloat16 h3 = __float2bfloat16_rn(v.w);
    __nv_bfloat16 l0 = __float2bfloat16_rn(v.x - __bfloat162float(h0));
    __nv_bfloat16 l1 = __float2bfloat16_rn(v.y - __bfloat162float(h1));
    __nv_bfloat16 l2 = __float2bfloat16_rn(v.z - __bfloat162float(h2));
    __nv_bfloat16 l3 = __float2bfloat16_rn(v.w - __bfloat162float(h3));
    uint32_t ha = (uint32_t)__bfloat16_as_ushort(h0) | ((uint32_t)__bfloat16_as_ushort(h1) << 16);
    uint32_t hb = (uint32_t)__bfloat16_as_ushort(h2) | ((uint32_t)__bfloat16_as_ushort(h3) << 16);
    uint32_t la = (uint32_t)__bfloat16_as_ushort(l0) | ((uint32_t)__bfloat16_as_ushort(l1) << 16);
    uint32_t lb = (uint32_t)__bfloat16_as_ushort(l2) | ((uint32_t)__bfloat16_as_ushort(l3) << 16);
    hi = (ull)ha | ((ull)hb << 32);
    lo = (ull)la | ((ull)lb << 32);
}

__device__ __forceinline__ void ldsm4(uint32_t* r, uint32_t addr) {
    asm volatile("ldmatrix.sync.aligned.m8n8.x4.shared.b16 {%0,%1,%2,%3}, [%4];"
                 : "=r"(r[0]), "=r"(r[1]), "=r"(r[2]), "=r"(r[3]) : "r"(addr));
}

__device__ __forceinline__ void mma16816(float* d, const uint32_t* a, const uint32_t* b) {
    asm volatile("mma.sync.aligned.m16n8k16.row.col.f32.bf16.bf16.f32 "
                 "{%0,%1,%2,%3}, {%4,%5,%6,%7}, {%8,%9}, {%0,%1,%2,%3};"
                 : "+f"(d[0]), "+f"(d[1]), "+f"(d[2]), "+f"(d[3])
                 : "r"(a[0]), "r"(a[1]), "r"(a[2]), "r"(a[3]), "r"(b[0]), "r"(b[1]));
}

__device__ __forceinline__ void bar_sync_named(int id) {
    asm volatile("bar.sync %0, 512;" :: "r"(id) : "memory");
}
__device__ __forceinline__ void bar_arrive_named(int id) {
    asm volatile("bar.arrive %0, 512;" :: "r"(id) : "memory");
}

// ---------------- shared MMA mainloop + epilogue ----------------
template<int KSTEPS, int SBv>
__device__ __forceinline__ void mma_loop(uint32_t aH, uint32_t aL,
                                         uint32_t bH, uint32_t bL, float acc[16][4]) {
    for (int ks = 0; ks < KSTEPS; ++ks) {
        uint32_t ah[4], al[4];
        ldsm4(ah, aH + ks * 32);
        ldsm4(al, aL + ks * 32);
        #pragma unroll
        for (int p = 0; p < 8; ++p) {
            uint32_t bh[4], bl[4];
            ldsm4(bh, bH + p * (16 * SBv * 2) + ks * 32);
            ldsm4(bl, bL + p * (16 * SBv * 2) + ks * 32);
            mma16816(acc[2*p],   ah, bh);
            mma16816(acc[2*p],   ah, bl);
            mma16816(acc[2*p],   al, bh);
            mma16816(acc[2*p+1], ah, bh + 2);
            mma16816(acc[2*p+1], ah, bl + 2);
            mma16816(acc[2*p+1], al, bh + 2);
        }
    }
}

__device__ __forceinline__ void store_frag(const float acc[16][4], const float* bs,
                                           float* out, int row_base, int g, int tq, int rmax) {
    int r0 = row_base + g, r1 = row_base + g + 8;
    float* o0 = out + (size_t)r0 * 128;
    float* o1 = out + (size_t)r1 * 128;
    bool w0 = r0 < rmax, w1 = r1 < rmax;
    #pragma unroll
    for (int p = 0; p < 16; ++p) {
        int c0 = p * 8 + tq * 2;
        if (w0) {
            float2 v = make_float2(fmaxf(acc[p][0] + bs[c0], 0.f),
                                   fmaxf(acc[p][1] + bs[c0+1], 0.f));
            *(float2*)(o0 + c0) = v;
        }
        if (w1) {
            float2 v = make_float2(fmaxf(acc[p][2] + bs[c0], 0.f),
                                   fmaxf(acc[p][3] + bs[c0+1], 0.f));
            *(float2*)(o1 + c0) = v;
        }
    }
}

// ---------------- pipelined edge GEMM kernels (512 thr: 8 producer + 8 consumer warps) ----
#define SB 136
#define MATB (128 * SB * 2)              // 34816
#define SM_BIAS 0
#define SM_A    512                      // stage s, part m at SM_A + (s*2+m)*MATB
#define SM_BH   (512 + 4 * MATB)
#define SM_BL   (SM_BH + MATB)
#define SM_TOTP (SM_BL + MATB)           // 209408

// FULL0=1 FULL1=2 FREE0=3 FREE1=4

// conv: h' = relu((agg[row] - h[e^1]) @ Wc + bc)
__global__ __launch_bounds__(512, 1) void k_conv_p(
    const float* __restrict__ h, const float* __restrict__ agg,
    const int* __restrict__ row, const float* __restrict__ W,
    const float* __restrict__ b, float* __restrict__ hout)
{
    extern __shared__ char smem[];
    uint32_t sbase = smem_u32(smem);
    int tid = threadIdx.x, wid = tid >> 5, lane = tid & 31;

    float* bs = (float*)(smem + SM_BIAS);
    if (tid < 128) bs[tid] = __ldg(&b[tid]);

    {   // B = W^T hi/lo
        int n = tid >> 2, kq = (tid & 3) * 32;
        char* Bh = smem + SM_BH; char* Bl = smem + SM_BL;
        #pragma unroll
        for (int c = 0; c < 8; ++c) {
            int k = kq + c * 4;
            float4 v = make_float4(__ldg(&W[(k+0)*128 + n]), __ldg(&W[(k+1)*128 + n]),
                                   __ldg(&W[(k+2)*128 + n]), __ldg(&W[(k+3)*128 + n]));
            ull hi, lo; split4(v, hi, lo);
            uint32_t off = (uint32_t)(n * SB + k) * 2;
            *(ull*)(Bh + off) = hi; *(ull*)(Bl + off) = lo;
        }
    }
    __syncthreads();

    const int NT = N_EDGES / 128;
    if (wid < 8) {
        // ---- producer ----
        int r = tid >> 1, kh = (tid & 1) * 64;
        const float4* agg4 = (const float4*)agg;
        const float4* h4   = (const float4*)h;
        int i = 0;
        for (int t = blockIdx.x; t < NT; t += gridDim.x, ++i) {
            int s = i & 1;
            if (i >= 2) bar_sync_named(3 + s);
            char* Ah = smem + SM_A + s * 2 * MATB;
            char* Al = Ah + MATB;
            int e = t * 128 + r;
            int rr = __ldg(&row[e]);
            const float4* ap = agg4 + (size_t)rr * 32 + (kh >> 2);
            const float4* rp = h4 + (size_t)(e ^ 1) * 32 + (kh >> 2);
            #pragma unroll
            for (int c = 0; c < 16; ++c) {
                float4 a = ap[c], rv = rp[c];
                float4 d = make_float4(a.x - rv.x, a.y - rv.y, a.z - rv.z, a.w - rv.w);
                ull hi, lo; split4(d, hi, lo);
                uint32_t off = (uint32_t)(r * SB + kh + c * 4) * 2;
                *(ull*)(Ah + off) = hi; *(ull*)(Al + off) = lo;
            }
            asm volatile("fence.cta;" ::: "memory");
            bar_arrive_named(1 + s);
        }
    } else {
        // ---- consumer ----
        int w = wid - 8, g = lane >> 2, tq = lane & 3;
        int a_row = (lane & 7) + ((lane >> 3) & 1) * 8;
        int a_col = (lane >> 4) * 8;
        uint32_t aoff = (uint32_t)((w * 16 + a_row) * SB + a_col) * 2;
        int b_row = (lane & 7) + ((lane >> 4) & 1) * 8;
        int b_col = ((lane >> 3) & 1) * 8;
        uint32_t bH = sbase + SM_BH + (uint32_t)(b_row * SB + b_col) * 2;
        uint32_t bL = bH + MATB;
        int i = 0;
        for (int t = blockIdx.x; t < NT; t += gridDim.x, ++i) {
            int s = i & 1;
            bar_sync_named(1 + s);
            uint32_t aH = sbase + SM_A + s * 2 * MATB + aoff;
            float acc[16][4];
            #pragma unroll
            for (int p = 0; p < 16; ++p)
                #pragma unroll
                for (int q = 0; q < 4; ++q) acc[p][q] = 0.f;
            mma_loop<8, SB>(aH, aH + MATB, bH, bL, acc);
            bar_arrive_named(3 + s);
            store_frag(acc, bs, hout, t * 128 + w * 16, g, tq, 0x7fffffff);
        }
    }
}

// init: h0 = relu([x[row] ; ea] @ W1 + b1), K=80
__global__ __launch_bounds__(512, 1) void k_init_p(
    const float* __restrict__ x, const float* __restrict__ ea,
    const int* __restrict__ row, const float* __restrict__ W,
    const float* __restrict__ b, float* __restrict__ hout)
{
    extern __shared__ char smem[];
    uint32_t sbase = smem_u32(smem);
    int tid = threadIdx.x, wid = tid >> 5, lane = tid & 31;

    float* bs = (float*)(smem + SM_BIAS);
    if (tid < 128) bs[tid] = __ldg(&b[tid]);

    {   // B = W1^T hi/lo, K=80
        int n = tid >> 2, kq = (tid & 3) * 32;
        char* Bh = smem + SM_BH; char* Bl = smem + SM_BL;
        #pragma unroll
        for (int c = 0; c < 8; ++c) {
            int k = kq + c * 4;
            if (k < 80) {
                float4 v = make_float4(__ldg(&W[(k+0)*128 + n]), __ldg(&W[(k+1)*128 + n]),
                                       __ldg(&W[(k+2)*128 + n]), __ldg(&W[(k+3)*128 + n]));
                ull hi, lo; split4(v, hi, lo);
                uint32_t off = (uint32_t)(n * SB + k) * 2;
                *(ull*)(Bh + off) = hi; *(ull*)(Bl + off) = lo;
            }
        }
    }
    __syncthreads();

    const int NT = N_EDGES / 128;
    if (wid < 8) {
        int r = tid >> 1;
        const float4* x4  = (const float4*)x;
        const float4* ea4 = (const float4*)ea;
        int i = 0;
        for (int t = blockIdx.x; t < NT; t += gridDim.x, ++i) {
            int s = i & 1;
            if (i >= 2) bar_sync_named(3 + s);
            char* Ah = smem + SM_A + s * 2 * MATB;
            char* Al = Ah + MATB;
            int e = t * 128 + r;
            int rr = __ldg(&row[e]);
            if ((tid & 1) == 0) {
                const float4* xp = x4 + (size_t)rr * 16;
                #pragma unroll
                for (int c = 0; c < 16; ++c) {
                    ull hi, lo; split4(xp[c], hi, lo);
                    uint32_t off = (uint32_t)(r * SB + c * 4) * 2;
                    *(ull*)(Ah + off) = hi; *(ull*)(Al + off) = lo;
                }
            } else {
                const float4* ep = ea4 + (size_t)e * 4;
                #pragma unroll
                for (int c = 0; c < 4; ++c) {
                    ull hi, lo; split4(ep[c], hi, lo);
                    uint32_t off = (uint32_t)(r * SB + 64 + c * 4) * 2;
                    *(ull*)(Ah + off) = hi; *(ull*)(Al + off) = lo;
                }
            }
            asm volatile("fence.cta;" ::: "memory");
            bar_arrive_named(1 + s);
        }
    } else {
        int w = wid - 8, g = lane >> 2, tq = lane & 3;
        int a_row = (lane & 7) + ((lane >> 3) & 1) * 8;
        int a_col = (lane >> 4) * 8;
        uint32_t aoff = (uint32_t)((w * 16 + a_row) * SB + a_col) * 2;
        int b_row = (lane & 7) + ((lane >> 4) & 1) * 8;
        int b_col = ((lane >> 3) & 1) * 8;
        uint32_t bH = sbase + SM_BH + (uint32_t)(b_row * SB + b_col) * 2;
        uint32_t bL = bH + MATB;
        int i = 0;
        for (int t = blockIdx.x; t < NT; t += gridDim.x, ++i) {
            int s = i & 1;
            bar_sync_named(1 + s);
            uint32_t aH = sbase + SM_A + s * 2 * MATB + aoff;
            float acc[16][4];
            #pragma unroll
            for (int p = 0; p < 16; ++p)
                #pragma unroll
                for (int q = 0; q < 4; ++q) acc[p][q] = 0.f;
            mma_loop<5, SB>(aH, aH + MATB, bH, bL, acc);
            bar_arrive_named(3 + s);
            store_frag(acc, bs, hout, t * 128 + w * 16, g, tq, 0x7fffffff);
        }
    }
}

// ---------------- final: out = relu([x ; s] @ W2 + b2), K=192 (MMA, non-pipelined) -------
#define SBF 200
#define MATF (128 * SBF * 2)             // 51200
#define FSM_BIAS 0
#define FSM_AHI  512
#define FSM_ALO  (FSM_AHI + MATF)
#define FSM_BHI  (FSM_ALO + MATF)
#define FSM_BLO  (FSM_BHI + MATF)
#define FSM_TOT  (FSM_BLO + MATF)        // 205312

__global__ __launch_bounds__(256, 1) void k_final_mma(
    const float* __restrict__ x, const float* __restrict__ agg,
    const float* __restrict__ W, const float* __restrict__ b, float* __restrict__ out)
{
    extern __shared__ char smem[];
    uint32_t sbase = smem_u32(smem);
    int tid = threadIdx.x, wid = tid >> 5, lane = tid & 31;
    int g = lane >> 2, tq = lane & 3;

    float* bs = (float*)(smem + FSM_BIAS);
    if (tid < 128) bs[tid] = __ldg(&b[tid]);

    {   // B = W2^T hi/lo: B[n][k] = W2[k*128+n], K=192
        int n = tid >> 1, kh = (tid & 1) * 96;
        char* Bh = smem + FSM_BHI; char* Bl = smem + FSM_BLO;
        #pragma unroll
        for (int c = 0; c < 24; ++c) {
            int k = kh + c * 4;
            float4 v = make_float4(__ldg(&W[(k+0)*128 + n]), __ldg(&W[(k+1)*128 + n]),
                                   __ldg(&W[(k+2)*128 + n]), __ldg(&W[(k+3)*128 + n]));
            ull hi, lo; split4(v, hi, lo);
            uint32_t off = (uint32_t)(n * SBF + k) * 2;
            *(ull*)(Bh + off) = hi; *(ull*)(Bl + off) = lo;
        }
    }
    __syncthreads();

    int a_row = (lane & 7) + ((lane >> 3) & 1) * 8;
    int a_col = (lane >> 4) * 8;
    uint32_t aH = sbase + FSM_AHI + (uint32_t)((wid * 16 + a_row) * SBF + a_col) * 2;
    uint32_t aL = aH + MATF;
    int b_row = (lane & 7) + ((lane >> 4) & 1) * 8;
    int b_col = ((lane >> 3) & 1) * 8;
    uint32_t bH = sbase + FSM_BHI + (uint32_t)(b_row * SBF + b_col) * 2;
    uint32_t bL = bH + MATF;

    const float4* x4   = (const float4*)x;
    const float4* agg4 = (const float4*)agg;
    char* Ah = smem + FSM_AHI; char* Al = smem + FSM_ALO;
    const int NT = (N_NODES + 127) / 128;

    for (int tile = blockIdx.x; tile < NT; tile += gridDim.x) {
        {   // fill A: row r = node, cols [x(64) ; agg(128)]
            int r = tid >> 1, half = tid & 1;
            int n = tile * 128 + r;
            #pragma unroll
            for (int c = 0; c < 24; ++c) {
                int k = half * 96 + c * 4;
                float4 v;
                if (n < N_NODES) {
                    if (k < 64) v = x4[(size_t)n * 16 + (k >> 2)];
                    else        v = agg4[(size_t)n * 32 + ((k - 64) >> 2)];
                } else v = make_float4(0.f, 0.f, 0.f, 0.f);
                ull hi, lo; split4(v, hi, lo);
                uint32_t off = (uint32_t)(r * SBF + k) * 2;
                *(ull*)(Ah + off) = hi; *(ull*)(Al + off) = lo;
            }
        }
        __syncthreads();
        float acc[16][4];
        #pragma unroll
        for (int p = 0; p < 16; ++p)
            #pragma unroll
            for (int q = 0; q < 4; ++q) acc[p][q] = 0.f;
        mma_loop<12, SBF>(aH, aL, bH, bL, acc);
        store_frag(acc, bs, out, tile * 128 + wid * 16, g, tq, N_NODES);
        __syncthreads();
    }
}

// ---------------- scatter-add h into agg by col (vector REDG) ----------------
__global__ __launch_bounds__(256) void k_scatter(
    const float* __restrict__ h, const int* __restrict__ col, float* __restrict__ agg)
{
    int idx = blockIdx.x * 256 + threadIdx.x;
    int e = idx >> 5, c = idx & 31;
    if (e >= N_EDGES) return;
    const float4* h4 = (const float4*)h;
    float4 v = h4[(size_t)e*32 + c];
    int n = __ldg(&col[e]);
    float* dst = agg + (size_t)n*HIDDEN + c*4;
    asm volatile("red.global.add.v4.f32 [%0], {%1, %2, %3, %4};"
                 :: "l"(dst), "f"(v.x), "f"(v.y), "f"(v.z), "f"(v.w) : "memory");
}

// ---------------- launch ----------------
extern "C" void kernel_launch(void* const* d_in, const int* in_sizes, int n_in,
                              void* d_out, int out_size)
{
    const float* x  = (const float*)d_in[0];
    const float* ea = (const float*)d_in[1];
    const int*   ei = (const int*)  d_in[2];
    const float* W1 = (const float*)d_in[3];
    const float* b1 = (const float*)d_in[4];
    const float* Wc = (const float*)d_in[5];
    const float* bc = (const float*)d_in[6];
    const float* W2 = (const float*)d_in[7];
    const float* b2 = (const float*)d_in[8];
    float* out = (float*)d_out;
    const int* row = ei;
    const int* col = ei + N_EDGES;

    void *ph_, *phn_, *pagg_;
    cudaGetSymbolAddress(&ph_,  g_h);
    cudaGetSymbolAddress(&phn_, g_hn);
    cudaGetSymbolAddress(&pagg_, g_agg);
    float* hb  = (float*)ph_;
    float* hnb = (float*)phn_;
    float* agg = (float*)pagg_;

    cudaFuncSetAttribute(k_init_p,    cudaFuncAttributeMaxDynamicSharedMemorySize, SM_TOTP);
    cudaFuncSetAttribute(k_conv_p,    cudaFuncAttributeMaxDynamicSharedMemorySize, SM_TOTP);
    cudaFuncSetAttribute(k_final_mma, cudaFuncAttributeMaxDynamicSharedMemorySize, FSM_TOT);

    k_init_p<<<148, 512, SM_TOTP>>>(x, ea, row, W1, b1, hb);

    float* cur = hb;
    float* nxt = hnb;
    for (int d = 0; d < DEPTH; ++d) {
        cudaMemsetAsync(agg, 0, (size_t)N_NODES * HIDDEN * sizeof(float));
        k_scatter<<<(N_EDGES * 32) / 256, 256>>>(cur, col, agg);
        k_conv_p<<<148, 512, SM_TOTP>>>(cur, agg, row,
                                        Wc + (size_t)d * HIDDEN * HIDDEN,
                                        bc + (size_t)d * HIDDEN, nxt);
        float* t = cur; cur = nxt; nxt = t;
    }

    cudaMemsetAsync(agg, 0, (size_t)N_NODES * HIDDEN * sizeof(float));
    k_scatter<<<(N_EDGES * 32) / 256, 256>>>(cur, col, agg);
    k_final_mma<<<148, 256, FSM_TOT>>>(x, agg, W2, b2, out);
}